// round 2
// baseline (speedup 1.0000x reference)
#include <cuda_runtime.h>
#include <cstdint>

#define DMODEL 1024
#define SEQ    2048
#define NB     2
#define NH     16
#define HD     64
#define MROWS  (NB * SEQ)          // 4096
#define LDA    68                  // padded smem row stride (floats)
#define ATTN_SMEM (3 * 64 * LDA * 4)

// ---------------- scratch (device globals: no runtime allocation allowed) ----
__device__ float g_q[NB * SEQ * DMODEL];
__device__ float g_k[NB * SEQ * DMODEL];
__device__ float g_v[NB * SEQ * DMODEL];
__device__ float g_ctx[NB * SEQ * DMODEL];

// ---------------- GEMM: C[M,1024] = A[M,1024] @ W[1024,1024]^T + bias (+resid)
// 64x64 block tile, BK=16, 256 threads, 4x4 per thread.
__global__ __launch_bounds__(256) void gemm_bias_kernel(
    const float* __restrict__ A, const float* __restrict__ W,
    const float* __restrict__ bias, const float* __restrict__ resid,
    float* __restrict__ C)
{
    __shared__ float As[16][LDA];
    __shared__ float Ws[16][LDA];

    const int tid = threadIdx.x;
    const int tx  = tid & 15;
    const int ty  = tid >> 4;
    const int bm  = blockIdx.x * 64;
    const int bn  = blockIdx.y * 64;

    const int lr = tid >> 2;         // 0..63 (row within tile)
    const int lc = (tid & 3) << 2;   // 0,4,8,12 (k within BK)

    const float* Ap = A + (size_t)(bm + lr) * DMODEL + lc;
    const float* Wp = W + (size_t)(bn + lr) * DMODEL + lc;

    float acc[4][4] = {};

    for (int k0 = 0; k0 < DMODEL; k0 += 16) {
        float4 a4 = *(const float4*)(Ap + k0);
        float4 w4 = *(const float4*)(Wp + k0);
        As[lc + 0][lr] = a4.x; As[lc + 1][lr] = a4.y;
        As[lc + 2][lr] = a4.z; As[lc + 3][lr] = a4.w;
        Ws[lc + 0][lr] = w4.x; Ws[lc + 1][lr] = w4.y;
        Ws[lc + 2][lr] = w4.z; Ws[lc + 3][lr] = w4.w;
        __syncthreads();
#pragma unroll
        for (int k = 0; k < 16; k++) {
            float4 av = *(const float4*)&As[k][ty << 2];
            float4 wv = *(const float4*)&Ws[k][tx << 2];
            float a[4] = {av.x, av.y, av.z, av.w};
            float w[4] = {wv.x, wv.y, wv.z, wv.w};
#pragma unroll
            for (int i = 0; i < 4; i++)
#pragma unroll
                for (int j = 0; j < 4; j++)
                    acc[i][j] = fmaf(a[i], w[j], acc[i][j]);
        }
        __syncthreads();
    }

#pragma unroll
    for (int i = 0; i < 4; i++) {
        const int row  = bm + (ty << 2) + i;
        const int colb = bn + (tx << 2);
        float4 ob;
        ob.x = acc[i][0] + bias[colb + 0];
        ob.y = acc[i][1] + bias[colb + 1];
        ob.z = acc[i][2] + bias[colb + 2];
        ob.w = acc[i][3] + bias[colb + 3];
        if (resid) {
            float4 r4 = *(const float4*)(resid + (size_t)row * DMODEL + colb);
            ob.x += r4.x; ob.y += r4.y; ob.z += r4.z; ob.w += r4.w;
        }
        *(float4*)(C + (size_t)row * DMODEL + colb) = ob;
    }
}

// ---------------- Flash-style attention per (qtile, head, batch) -------------
// Each head slab is contiguous [2048][64]. Mask int32: nonzero => -1e9.
__global__ __launch_bounds__(256) void attn_kernel(
    const float* __restrict__ qg, const float* __restrict__ kg,
    const float* __restrict__ vg, const int* __restrict__ mask,
    float* __restrict__ ctx)
{
    extern __shared__ float sm[];
    float* Qst = sm;                 // [64 d][LDA] transposed: Qst[d][r]
    float* Kst = Qst + 64 * LDA;     // [64 d][LDA] transposed: Kst[d][c]; reused as Ps[r][c]
    float* Vs  = Kst + 64 * LDA;     // [64 c][LDA] row-major: Vs[c][dv]

    const int tid = threadIdx.x;
    const int tx  = tid & 15;
    const int ty  = tid >> 4;
    const int qt = blockIdx.x, h = blockIdx.y, b = blockIdx.z;

    const size_t head_off = (size_t)b * (SEQ * DMODEL) + (size_t)h * (SEQ * HD);
    const float* qh = qg + head_off + (size_t)qt * (64 * HD);
    const float* kh = kg + head_off;
    const float* vh = vg + head_off;
    const int* mrow = mask + (size_t)b * SEQ * SEQ + (size_t)(qt * 64) * SEQ;

    // Load Q tile (contiguous 4096 floats), store transposed
#pragma unroll
    for (int p = 0; p < 4; p++) {
        int q4 = tid + p * 256;          // float4 index 0..1023
        int r  = q4 >> 4;                // 0..63
        int d0 = (q4 & 15) << 2;         // 0..60
        float4 t = *(const float4*)(qh + (size_t)q4 * 4);
        Qst[(d0 + 0) * LDA + r] = t.x;
        Qst[(d0 + 1) * LDA + r] = t.y;
        Qst[(d0 + 2) * LDA + r] = t.z;
        Qst[(d0 + 3) * LDA + r] = t.w;
    }

    float m_i[4], l_i[4], acc[4][4];
#pragma unroll
    for (int i = 0; i < 4; i++) {
        m_i[i] = -1e30f; l_i[i] = 0.f;
#pragma unroll
        for (int j = 0; j < 4; j++) acc[i][j] = 0.f;
    }

    for (int kt = 0; kt < SEQ / 64; kt++) {
        const float* kp = kh + (size_t)kt * (64 * HD);
        const float* vp = vh + (size_t)kt * (64 * HD);

        __syncthreads();   // previous iter readers of Kst(=Ps)/Vs done; Qst store visible
#pragma unroll
        for (int p = 0; p < 4; p++) {
            int q4 = tid + p * 256;
            int r  = q4 >> 4;
            int d0 = (q4 & 15) << 2;
            float4 t = *(const float4*)(kp + (size_t)q4 * 4);
            Kst[(d0 + 0) * LDA + r] = t.x;
            Kst[(d0 + 1) * LDA + r] = t.y;
            Kst[(d0 + 2) * LDA + r] = t.z;
            Kst[(d0 + 3) * LDA + r] = t.w;
            float4 u = *(const float4*)(vp + (size_t)q4 * 4);
            *(float4*)&Vs[r * LDA + d0] = u;
        }
        __syncthreads();

        // S = Q @ K^T (per-thread 4x4)
        float s[4][4] = {};
#pragma unroll
        for (int d = 0; d < 64; d++) {
            float4 qv = *(const float4*)&Qst[d * LDA + (ty << 2)];
            float4 kv = *(const float4*)&Kst[d * LDA + (tx << 2)];
            float a[4] = {qv.x, qv.y, qv.z, qv.w};
            float w[4] = {kv.x, kv.y, kv.z, kv.w};
#pragma unroll
            for (int i = 0; i < 4; i++)
#pragma unroll
                for (int j = 0; j < 4; j++)
                    s[i][j] = fmaf(a[i], w[j], s[i][j]);
        }

        // scale + mask (mask nonzero => exactly -1e9, matching reference)
        const int kbase = kt * 64 + (tx << 2);
#pragma unroll
        for (int i = 0; i < 4; i++) {
            int4 mk = *(const int4*)(mrow + (size_t)((ty << 2) + i) * SEQ + kbase);
            s[i][0] = mk.x ? -1e9f : s[i][0] * 0.125f;
            s[i][1] = mk.y ? -1e9f : s[i][1] * 0.125f;
            s[i][2] = mk.z ? -1e9f : s[i][2] * 0.125f;
            s[i][3] = mk.w ? -1e9f : s[i][3] * 0.125f;
        }

        // online softmax (row groups live in 16-lane halves of a warp)
#pragma unroll
        for (int i = 0; i < 4; i++) {
            float mx = fmaxf(fmaxf(s[i][0], s[i][1]), fmaxf(s[i][2], s[i][3]));
#pragma unroll
            for (int o = 8; o >= 1; o >>= 1)
                mx = fmaxf(mx, __shfl_xor_sync(0xffffffffu, mx, o));
            float mnew  = fmaxf(m_i[i], mx);
            float alpha = __expf(m_i[i] - mnew);
            m_i[i] = mnew;
            float rs = 0.f;
#pragma unroll
            for (int j = 0; j < 4; j++) {
                s[i][j] = __expf(s[i][j] - mnew);
                rs += s[i][j];
            }
#pragma unroll
            for (int o = 8; o >= 1; o >>= 1)
                rs += __shfl_xor_sync(0xffffffffu, rs, o);
            l_i[i] = l_i[i] * alpha + rs;
#pragma unroll
            for (int j = 0; j < 4; j++) acc[i][j] *= alpha;
        }

        __syncthreads();   // all threads done reading Kst (S phase)
        float* Ps = Kst;   // reuse K buffer for P[r][c]
#pragma unroll
        for (int i = 0; i < 4; i++) {
            float4 pv = make_float4(s[i][0], s[i][1], s[i][2], s[i][3]);
            *(float4*)&Ps[((ty << 2) + i) * LDA + (tx << 2)] = pv;
        }
        __syncthreads();

        // acc += P @ V
#pragma unroll
        for (int c = 0; c < 64; c++) {
            float4 vv = *(const float4*)&Vs[c * LDA + (tx << 2)];
            float p0 = Ps[((ty << 2) + 0) * LDA + c];
            float p1 = Ps[((ty << 2) + 1) * LDA + c];
            float p2 = Ps[((ty << 2) + 2) * LDA + c];
            float p3 = Ps[((ty << 2) + 3) * LDA + c];
            acc[0][0] = fmaf(p0, vv.x, acc[0][0]);
            acc[0][1] = fmaf(p0, vv.y, acc[0][1]);
            acc[0][2] = fmaf(p0, vv.z, acc[0][2]);
            acc[0][3] = fmaf(p0, vv.w, acc[0][3]);
            acc[1][0] = fmaf(p1, vv.x, acc[1][0]);
            acc[1][1] = fmaf(p1, vv.y, acc[1][1]);
            acc[1][2] = fmaf(p1, vv.z, acc[1][2]);
            acc[1][3] = fmaf(p1, vv.w, acc[1][3]);
            acc[2][0] = fmaf(p2, vv.x, acc[2][0]);
            acc[2][1] = fmaf(p2, vv.y, acc[2][1]);
            acc[2][2] = fmaf(p2, vv.z, acc[2][2]);
            acc[2][3] = fmaf(p2, vv.w, acc[2][3]);
            acc[3][0] = fmaf(p3, vv.x, acc[3][0]);
            acc[3][1] = fmaf(p3, vv.y, acc[3][1]);
            acc[3][2] = fmaf(p3, vv.z, acc[3][2]);
            acc[3][3] = fmaf(p3, vv.w, acc[3][3]);
        }
    }

    // ctx[b][s2][h*64+dv] = acc / l   (head-concat layout for the out-projection)
#pragma unroll
    for (int i = 0; i < 4; i++) {
        int r = qt * 64 + (ty << 2) + i;
        float inv = 1.0f / l_i[i];
        float4 o = make_float4(acc[i][0] * inv, acc[i][1] * inv,
                               acc[i][2] * inv, acc[i][3] * inv);
        *(float4*)(ctx + (size_t)b * (SEQ * DMODEL) + (size_t)r * DMODEL
                   + h * HD + (tx << 2)) = o;
    }
}

// ---------------- LayerNorm (in place on d_out), one block per row ----------
__global__ __launch_bounds__(256) void ln_kernel(
    float* __restrict__ x, const float* __restrict__ gamma,
    const float* __restrict__ beta)
{
    __shared__ float ss[8], ssq[8];
    const int row = blockIdx.x;
    const int tid = threadIdx.x;
    float* xr = x + (size_t)row * DMODEL;

    float4 v = *(const float4*)(xr + tid * 4);
    float s  = v.x + v.y + v.z + v.w;
    float sq = v.x * v.x + v.y * v.y + v.z * v.z + v.w * v.w;
#pragma unroll
    for (int o = 16; o >= 1; o >>= 1) {
        s  += __shfl_xor_sync(0xffffffffu, s,  o);
        sq += __shfl_xor_sync(0xffffffffu, sq, o);
    }
    if ((tid & 31) == 0) { ss[tid >> 5] = s; ssq[tid >> 5] = sq; }
    __syncthreads();
    float tot = 0.f, totq = 0.f;
#pragma unroll
    for (int i = 0; i < 8; i++) { tot += ss[i]; totq += ssq[i]; }

    const float mean = tot * (1.0f / DMODEL);
    const float var  = totq * (1.0f / DMODEL) - mean * mean;
    const float rstd = rsqrtf(var + 1e-5f);

    float4 g = *(const float4*)(gamma + tid * 4);
    float4 bb = *(const float4*)(beta + tid * 4);
    float4 o;
    o.x = (v.x - mean) * rstd * g.x + bb.x;
    o.y = (v.y - mean) * rstd * g.y + bb.y;
    o.z = (v.z - mean) * rstd * g.z + bb.z;
    o.w = (v.w - mean) * rstd * g.w + bb.w;
    *(float4*)(xr + tid * 4) = o;
}

// ---------------- launch -----------------------------------------------------
extern "C" void kernel_launch(void* const* d_in, const int* in_sizes, int n_in,
                              void* d_out, int out_size) {
    const float* Q  = (const float*)d_in[0];
    const float* K  = (const float*)d_in[1];
    const float* V  = (const float*)d_in[2];
    const int*   mask = (const int*)d_in[3];
    const float* wq = (const float*)d_in[4];
    const float* bq = (const float*)d_in[5];
    const float* wk = (const float*)d_in[6];
    const float* bk = (const float*)d_in[7];
    const float* wv = (const float*)d_in[8];
    const float* bv = (const float*)d_in[9];
    const float* wo = (const float*)d_in[10];
    const float* bo = (const float*)d_in[11];
    const float* gamma = (const float*)d_in[12];
    const float* beta  = (const float*)d_in[13];
    float* out = (float*)d_out;

    float *gq, *gk, *gv, *gctx;
    cudaGetSymbolAddress((void**)&gq,   g_q);
    cudaGetSymbolAddress((void**)&gk,   g_k);
    cudaGetSymbolAddress((void**)&gv,   g_v);
    cudaGetSymbolAddress((void**)&gctx, g_ctx);

    cudaFuncSetAttribute(attn_kernel,
                         cudaFuncAttributeMaxDynamicSharedMemorySize, ATTN_SMEM);

    dim3 gg(MROWS / 64, DMODEL / 64);   // (64, 16)
    gemm_bias_kernel<<<gg, 256>>>(Q, wq, bq, nullptr, gq);
    gemm_bias_kernel<<<gg, 256>>>(K, wk, bk, nullptr, gk);
    gemm_bias_kernel<<<gg, 256>>>(V, wv, bv, nullptr, gv);

    attn_kernel<<<dim3(SEQ / 64, NH, NB), 256, ATTN_SMEM>>>(gq, gk, gv, mask, gctx);

    gemm_bias_kernel<<<gg, 256>>>(gctx, wo, bo, Q, out);
    ln_kernel<<<MROWS, 256>>>(out, gamma, beta);
}

// round 4
// speedup vs baseline: 3.4910x; 3.4910x over previous
#include <cuda_runtime.h>
#include <cuda_bf16.h>
#include <cstdint>

#define DMODEL 1024
#define SEQ    2048
#define NB     2
#define NH     16
#define HD     64
#define MROWS  (NB * SEQ)          // 4096

// ====================== warp-mma helpers (base sm_103 features only) =========
__device__ __forceinline__ uint32_t smem_u32(const void* p) {
    uint32_t a;
    asm("{ .reg .u64 t; cvta.to.shared.u64 t, %1; cvt.u32.u64 %0, t; }"
        : "=r"(a) : "l"(p));
    return a;
}
__device__ __forceinline__ void ldsm4(uint32_t* r, uint32_t addr) {
    asm volatile("ldmatrix.sync.aligned.m8n8.x4.shared.b16 {%0,%1,%2,%3}, [%4];"
                 : "=r"(r[0]), "=r"(r[1]), "=r"(r[2]), "=r"(r[3]) : "r"(addr));
}
__device__ __forceinline__ void ldsm4t(uint32_t* r, uint32_t addr) {
    asm volatile("ldmatrix.sync.aligned.m8n8.x4.trans.shared.b16 {%0,%1,%2,%3}, [%4];"
                 : "=r"(r[0]), "=r"(r[1]), "=r"(r[2]), "=r"(r[3]) : "r"(addr));
}
__device__ __forceinline__ void mma_bf16(float* c, const uint32_t* a, const uint32_t* b) {
    asm volatile(
        "mma.sync.aligned.m16n8k16.row.col.f32.bf16.bf16.f32 "
        "{%0,%1,%2,%3}, {%4,%5,%6,%7}, {%8,%9}, {%0,%1,%2,%3};"
        : "+f"(c[0]), "+f"(c[1]), "+f"(c[2]), "+f"(c[3])
        : "r"(a[0]), "r"(a[1]), "r"(a[2]), "r"(a[3]), "r"(b[0]), "r"(b[1]));
}
__device__ __forceinline__ uint32_t pack2(float lo, float hi) {
    __nv_bfloat162 t = __floats2bfloat162_rn(lo, hi);
    return *reinterpret_cast<uint32_t*>(&t);
}
// exp(x) for x <= 0 on the fma/alu pipes (keeps MUFU free). rel err ~1e-5.
__device__ __forceinline__ float fexp(float x) {
    float t = fmaxf(x * 1.44269504088896f, -126.0f);
    int   e = __float2int_rd(t);
    float f = t - (float)e;
    float p = 1.53569209e-4f;
    p = fmaf(p, f, 1.33978521e-3f);
    p = fmaf(p, f, 9.61817249e-3f);
    p = fmaf(p, f, 5.55041087e-2f);
    p = fmaf(p, f, 2.40226507e-1f);
    p = fmaf(p, f, 6.93147181e-1f);
    p = fmaf(p, f, 1.0f);
    return p * __int_as_float((e + 127) << 23);
}

// ====================== scratch ==============================================
__device__ __nv_bfloat16 g_qb [MROWS * DMODEL];   // bf16(Q input)
__device__ __nv_bfloat16 g_kb [MROWS * DMODEL];
__device__ __nv_bfloat16 g_vb [MROWS * DMODEL];
__device__ __nv_bfloat16 g_q2 [MROWS * DMODEL];   // projected q (bf16)
__device__ __nv_bfloat16 g_k2 [MROWS * DMODEL];
__device__ __nv_bfloat16 g_v2 [MROWS * DMODEL];
__device__ __nv_bfloat16 g_ctx[MROWS * DMODEL];
__device__ __nv_bfloat16 g_wqb[DMODEL * DMODEL];
__device__ __nv_bfloat16 g_wkb[DMODEL * DMODEL];
__device__ __nv_bfloat16 g_wvb[DMODEL * DMODEL];
__device__ __nv_bfloat16 g_wob[DMODEL * DMODEL];

// ====================== fp32 -> bf16 convert =================================
__global__ __launch_bounds__(256) void f2bf_kernel(
    const float* __restrict__ in, __nv_bfloat16* __restrict__ out, int n4)
{
    int i = blockIdx.x * 256 + threadIdx.x;
    if (i < n4) {
        float4 v = ((const float4*)in)[i];
        ((__nv_bfloat162*)out)[i * 2 + 0] = __floats2bfloat162_rn(v.x, v.y);
        ((__nv_bfloat162*)out)[i * 2 + 1] = __floats2bfloat162_rn(v.z, v.w);
    }
}

// ====================== mma GEMM =============================================
// C[4096,1024] = A[4096,1024] @ W[1024,1024]^T + bias, bf16 in, f32 accum.
// Cb != null -> bf16 out ; else Cf (f32) with residual add.
#define GSTR 40   // smem row stride in bf16 (32 + 8 pad): 80B, /16B = 5 (odd) -> conflict-free ldmatrix
__global__ __launch_bounds__(256) void gemm_mma_kernel(
    const __nv_bfloat16* __restrict__ A, const __nv_bfloat16* __restrict__ W,
    const float* __restrict__ bias, const float* __restrict__ resid,
    float* __restrict__ Cf, __nv_bfloat16* __restrict__ Cb)
{
    __shared__ __nv_bfloat16 As[2][128 * GSTR];
    __shared__ __nv_bfloat16 Ws[2][128 * GSTR];

    const int tid = threadIdx.x;
    const int wid = tid >> 5, lid = tid & 31;
    const int wm = wid >> 2, wn = wid & 3;       // warp tile: 64(M) x 32(N)
    const int bm = blockIdx.x * 128, bn = blockIdx.y * 128;

    const uint32_t as_u = smem_u32(As), ws_u = smem_u32(Ws);

    float acc[4][4][4] = {};

    auto load_tile = [&](int buf, int k0) {
#pragma unroll
        for (int i = 0; i < 2; i++) {
            int idx = tid + i * 256;             // 0..511
            int row = idx >> 2, c8 = (idx & 3) << 3;
            *(uint4*)&As[buf][row * GSTR + c8] =
                *(const uint4*)(A + (size_t)(bm + row) * DMODEL + k0 + c8);
            *(uint4*)&Ws[buf][row * GSTR + c8] =
                *(const uint4*)(W + (size_t)(bn + row) * DMODEL + k0 + c8);
        }
    };

    load_tile(0, 0);
    __syncthreads();

    for (int k0 = 0; k0 < DMODEL; k0 += 32) {
        const int buf = (k0 >> 5) & 1;
        if (k0 + 32 < DMODEL) load_tile(buf ^ 1, k0 + 32);

        const uint32_t ab = as_u + (uint32_t)buf * (128 * GSTR * 2);
        const uint32_t wb = ws_u + (uint32_t)buf * (128 * GSTR * 2);
#pragma unroll
        for (int ks = 0; ks < 2; ks++) {
            uint32_t aF[4][4];
#pragma unroll
            for (int mt = 0; mt < 4; mt++)
                ldsm4(aF[mt], ab + (((wm * 64 + mt * 16 + (lid & 15)) * GSTR
                                     + ks * 16 + (lid >> 4) * 8) << 1));
            uint32_t bF[2][4];
#pragma unroll
            for (int p = 0; p < 2; p++)
                ldsm4(bF[p], wb + (((wn * 32 + p * 16 + ((lid >> 4) & 1) * 8 + (lid & 7)) * GSTR
                                    + ks * 16 + ((lid >> 3) & 1) * 8) << 1));
#pragma unroll
            for (int mt = 0; mt < 4; mt++)
#pragma unroll
                for (int nt = 0; nt < 4; nt++)
                    mma_bf16(acc[mt][nt], aF[mt], &bF[nt >> 1][(nt & 1) * 2]);
        }
        __syncthreads();
    }

    const int lr = lid >> 2, lc2 = (lid & 3) * 2;
#pragma unroll
    for (int mt = 0; mt < 4; mt++) {
        const int row0 = bm + wm * 64 + mt * 16 + lr;
#pragma unroll
        for (int nt = 0; nt < 4; nt++) {
            const int col = bn + wn * 32 + nt * 8 + lc2;
            const float b0 = bias[col], b1 = bias[col + 1];
            float v00 = acc[mt][nt][0] + b0, v01 = acc[mt][nt][1] + b1;
            float v10 = acc[mt][nt][2] + b0, v11 = acc[mt][nt][3] + b1;
            if (Cf) {
                float2 r0 = *(const float2*)(resid + (size_t)row0 * DMODEL + col);
                float2 r1 = *(const float2*)(resid + (size_t)(row0 + 8) * DMODEL + col);
                *(float2*)(Cf + (size_t)row0 * DMODEL + col)       = make_float2(v00 + r0.x, v01 + r0.y);
                *(float2*)(Cf + (size_t)(row0 + 8) * DMODEL + col) = make_float2(v10 + r1.x, v11 + r1.y);
            } else {
                *(uint32_t*)(Cb + (size_t)row0 * DMODEL + col)       = pack2(v00, v01);
                *(uint32_t*)(Cb + (size_t)(row0 + 8) * DMODEL + col) = pack2(v10, v11);
            }
        }
    }
}

// ====================== mma flash attention ==================================
// 4 warps, 128 threads; CTA = 64 q-rows of one (head, batch); warp = 16 rows.
// Head slab contiguous [2048][64] (reshape-based split). Mask int32 nonzero -> -1e9.
#define ASTR 72   // smem row stride bf16 (64+8): 144B, /16B = 9 (odd) -> conflict-free
__global__ __launch_bounds__(128) void attn_mma_kernel(
    const __nv_bfloat16* __restrict__ qg, const __nv_bfloat16* __restrict__ kg,
    const __nv_bfloat16* __restrict__ vg, const int* __restrict__ mask,
    __nv_bfloat16* __restrict__ ctx)
{
    __shared__ __nv_bfloat16 Qs[64 * ASTR];
    __shared__ __nv_bfloat16 Ks[64 * ASTR];
    __shared__ __nv_bfloat16 Vs[64 * ASTR];

    const int tid = threadIdx.x;
    const int wid = tid >> 5, lid = tid & 31;
    const int qt = blockIdx.x, h = blockIdx.y, b = blockIdx.z;

    const size_t head_off = (size_t)b * (SEQ * DMODEL) + (size_t)h * (SEQ * HD);
    const __nv_bfloat16* qh = qg + head_off + (size_t)qt * (64 * HD);
    const __nv_bfloat16* kh = kg + head_off;
    const __nv_bfloat16* vh = vg + head_off;

    const uint32_t qs_u = smem_u32(Qs), ks_u = smem_u32(Ks), vs_u = smem_u32(Vs);

    // load Q tile (64 x 64 bf16, contiguous)
#pragma unroll
    for (int i = 0; i < 4; i++) {
        int idx = tid + i * 128;
        int row = idx >> 3, c8 = (idx & 7) << 3;
        *(uint4*)&Qs[row * ASTR + c8] = *(const uint4*)(qh + row * HD + c8);
    }
    __syncthreads();

    uint32_t aQ[4][4];
#pragma unroll
    for (int kk = 0; kk < 4; kk++)
        ldsm4(aQ[kk], qs_u + (((wid * 16 + (lid & 15)) * ASTR
                               + kk * 16 + (lid >> 4) * 8) << 1));

    float accO[8][4] = {};
    float m0 = -1e30f, m1 = -1e30f, l0 = 0.f, l1 = 0.f;

    const int r0l = qt * 64 + wid * 16 + (lid >> 2);   // this lane's q rows
    const int* mk0 = mask + (size_t)b * SEQ * SEQ + (size_t)r0l * SEQ;
    const int* mk1 = mk0 + 8 * SEQ;

    const int nhib = (lid >> 4) & 1;   // ldmatrix group bits
    const int khib = (lid >> 3) & 1;
    const int l7   = lid & 7;

    for (int kt = 0; kt < SEQ / 64; kt++) {
        __syncthreads();
        const __nv_bfloat16* kp = kh + (size_t)kt * (64 * HD);
        const __nv_bfloat16* vp = vh + (size_t)kt * (64 * HD);
#pragma unroll
        for (int i = 0; i < 4; i++) {
            int idx = tid + i * 128;
            int row = idx >> 3, c8 = (idx & 7) << 3;
            *(uint4*)&Ks[row * ASTR + c8] = *(const uint4*)(kp + row * HD + c8);
            *(uint4*)&Vs[row * ASTR + c8] = *(const uint4*)(vp + row * HD + c8);
        }
        __syncthreads();

        // ---- S = Q K^T ----
        float accS[8][4] = {};
#pragma unroll
        for (int kk = 0; kk < 4; kk++) {
            uint32_t bK[4][4];
#pragma unroll
            for (int p = 0; p < 4; p++)
                ldsm4(bK[p], ks_u + (((p * 16 + nhib * 8 + l7) * ASTR
                                      + kk * 16 + khib * 8) << 1));
#pragma unroll
            for (int nt = 0; nt < 8; nt++)
                mma_bf16(accS[nt], aQ[kk], &bK[nt >> 1][(nt & 1) * 2]);
        }

        // ---- mask + scale + online softmax ----
        const int cb = kt * 64 + 2 * (lid & 3);
        float mx0 = -3e38f, mx1 = -3e38f;
#pragma unroll
        for (int nt = 0; nt < 8; nt++) {
            int c = cb + nt * 8;
            int2 ma = *(const int2*)(mk0 + c);
            int2 mb = *(const int2*)(mk1 + c);
            accS[nt][0] = ma.x ? -1e9f : accS[nt][0] * 0.125f;
            accS[nt][1] = ma.y ? -1e9f : accS[nt][1] * 0.125f;
            accS[nt][2] = mb.x ? -1e9f : accS[nt][2] * 0.125f;
            accS[nt][3] = mb.y ? -1e9f : accS[nt][3] * 0.125f;
            mx0 = fmaxf(mx0, fmaxf(accS[nt][0], accS[nt][1]));
            mx1 = fmaxf(mx1, fmaxf(accS[nt][2], accS[nt][3]));
        }
        mx0 = fmaxf(mx0, __shfl_xor_sync(0xffffffffu, mx0, 1));
        mx0 = fmaxf(mx0, __shfl_xor_sync(0xffffffffu, mx0, 2));
        mx1 = fmaxf(mx1, __shfl_xor_sync(0xffffffffu, mx1, 1));
        mx1 = fmaxf(mx1, __shfl_xor_sync(0xffffffffu, mx1, 2));

        const float mn0 = fmaxf(m0, mx0), mn1 = fmaxf(m1, mx1);
        const float al0 = fexp(m0 - mn0), al1 = fexp(m1 - mn1);
        m0 = mn0; m1 = mn1;

        float rs0 = 0.f, rs1 = 0.f;
#pragma unroll
        for (int nt = 0; nt < 8; nt++) {
            accS[nt][0] = fexp(accS[nt][0] - m0);
            accS[nt][1] = fexp(accS[nt][1] - m0);
            accS[nt][2] = fexp(accS[nt][2] - m1);
            accS[nt][3] = fexp(accS[nt][3] - m1);
            rs0 += accS[nt][0] + accS[nt][1];
            rs1 += accS[nt][2] + accS[nt][3];
        }
        rs0 += __shfl_xor_sync(0xffffffffu, rs0, 1);
        rs0 += __shfl_xor_sync(0xffffffffu, rs0, 2);
        rs1 += __shfl_xor_sync(0xffffffffu, rs1, 1);
        rs1 += __shfl_xor_sync(0xffffffffu, rs1, 2);
        l0 = l0 * al0 + rs0;
        l1 = l1 * al1 + rs1;
#pragma unroll
        for (int nt = 0; nt < 8; nt++) {
            accO[nt][0] *= al0; accO[nt][1] *= al0;
            accO[nt][2] *= al1; accO[nt][3] *= al1;
        }

        // ---- P (register C-frags) -> bf16 A-frags ----
        uint32_t aP[4][4];
#pragma unroll
        for (int kk = 0; kk < 4; kk++) {
            aP[kk][0] = pack2(accS[2 * kk][0],     accS[2 * kk][1]);
            aP[kk][1] = pack2(accS[2 * kk][2],     accS[2 * kk][3]);
            aP[kk][2] = pack2(accS[2 * kk + 1][0], accS[2 * kk + 1][1]);
            aP[kk][3] = pack2(accS[2 * kk + 1][2], accS[2 * kk + 1][3]);
        }

        // ---- O += P V ----
#pragma unroll
        for (int kk = 0; kk < 4; kk++) {
            uint32_t bV[4][4];
#pragma unroll
            for (int p = 0; p < 4; p++)
                ldsm4t(bV[p], vs_u + (((kk * 16 + khib * 8 + l7) * ASTR
                                       + p * 16 + nhib * 8) << 1));
#pragma unroll
            for (int nt = 0; nt < 8; nt++)
                mma_bf16(accO[nt], aP[kk], &bV[nt >> 1][(nt & 1) * 2]);
        }
    }

    // ---- write ctx (head-concat layout) ----
    const float inv0 = 1.f / l0, inv1 = 1.f / l1;
    __nv_bfloat16* crow0 = ctx + (size_t)b * (SEQ * DMODEL) + (size_t)r0l * DMODEL + h * HD;
    __nv_bfloat16* crow1 = crow0 + (size_t)8 * DMODEL;
#pragma unroll
    for (int nt = 0; nt < 8; nt++) {
        int c = nt * 8 + 2 * (lid & 3);
        *(uint32_t*)(crow0 + c) = pack2(accO[nt][0] * inv0, accO[nt][1] * inv0);
        *(uint32_t*)(crow1 + c) = pack2(accO[nt][2] * inv1, accO[nt][3] * inv1);
    }
}

// ====================== LayerNorm ===========================================
__global__ __launch_bounds__(256) void ln_kernel(
    float* __restrict__ x, const float* __restrict__ gamma,
    const float* __restrict__ beta)
{
    __shared__ float ss[8], ssq[8];
    const int row = blockIdx.x;
    const int tid = threadIdx.x;
    float* xr = x + (size_t)row * DMODEL;

    float4 v = *(const float4*)(xr + tid * 4);
    float s  = v.x + v.y + v.z + v.w;
    float sq = v.x * v.x + v.y * v.y + v.z * v.z + v.w * v.w;
#pragma unroll
    for (int o = 16; o >= 1; o >>= 1) {
        s  += __shfl_xor_sync(0xffffffffu, s,  o);
        sq += __shfl_xor_sync(0xffffffffu, sq, o);
    }
    if ((tid & 31) == 0) { ss[tid >> 5] = s; ssq[tid >> 5] = sq; }
    __syncthreads();
    float tot = 0.f, totq = 0.f;
#pragma unroll
    for (int i = 0; i < 8; i++) { tot += ss[i]; totq += ssq[i]; }

    const float mean = tot * (1.0f / DMODEL);
    const float var  = totq * (1.0f / DMODEL) - mean * mean;
    const float rstd = rsqrtf(var + 1e-5f);

    float4 g = *(const float4*)(gamma + tid * 4);
    float4 bb = *(const float4*)(beta + tid * 4);
    float4 o;
    o.x = (v.x - mean) * rstd * g.x + bb.x;
    o.y = (v.y - mean) * rstd * g.y + bb.y;
    o.z = (v.z - mean) * rstd * g.z + bb.z;
    o.w = (v.w - mean) * rstd * g.w + bb.w;
    *(float4*)(xr + tid * 4) = o;
}

// ====================== launch ==============================================
extern "C" void kernel_launch(void* const* d_in, const int* in_sizes, int n_in,
                              void* d_out, int out_size) {
    const float* Q  = (const float*)d_in[0];
    const float* K  = (const float*)d_in[1];
    const float* V  = (const float*)d_in[2];
    const int*   mask = (const int*)d_in[3];
    const float* wq = (const float*)d_in[4];
    const float* bq = (const float*)d_in[5];
    const float* wk = (const float*)d_in[6];
    const float* bk = (const float*)d_in[7];
    const float* wv = (const float*)d_in[8];
    const float* bv = (const float*)d_in[9];
    const float* wo = (const float*)d_in[10];
    const float* bo = (const float*)d_in[11];
    const float* gamma = (const float*)d_in[12];
    const float* beta  = (const float*)d_in[13];
    float* out = (float*)d_out;

    __nv_bfloat16 *gqb, *gkb, *gvb, *gq2, *gk2, *gv2, *gctx;
    __nv_bfloat16 *gwqb, *gwkb, *gwvb, *gwob;
    cudaGetSymbolAddress((void**)&gqb,  g_qb);
    cudaGetSymbolAddress((void**)&gkb,  g_kb);
    cudaGetSymbolAddress((void**)&gvb,  g_vb);
    cudaGetSymbolAddress((void**)&gq2,  g_q2);
    cudaGetSymbolAddress((void**)&gk2,  g_k2);
    cudaGetSymbolAddress((void**)&gv2,  g_v2);
    cudaGetSymbolAddress((void**)&gctx, g_ctx);
    cudaGetSymbolAddress((void**)&gwqb, g_wqb);
    cudaGetSymbolAddress((void**)&gwkb, g_wkb);
    cudaGetSymbolAddress((void**)&gwvb, g_wvb);
    cudaGetSymbolAddress((void**)&gwob, g_wob);

    const int nin4 = MROWS * DMODEL / 4;
    const int nw4  = DMODEL * DMODEL / 4;
    f2bf_kernel<<<(nin4 + 255) / 256, 256>>>(Q,  gqb,  nin4);
    f2bf_kernel<<<(nin4 + 255) / 256, 256>>>(K,  gkb,  nin4);
    f2bf_kernel<<<(nin4 + 255) / 256, 256>>>(V,  gvb,  nin4);
    f2bf_kernel<<<(nw4 + 255) / 256, 256>>>(wq, gwqb, nw4);
    f2bf_kernel<<<(nw4 + 255) / 256, 256>>>(wk, gwkb, nw4);
    f2bf_kernel<<<(nw4 + 255) / 256, 256>>>(wv, gwvb, nw4);
    f2bf_kernel<<<(nw4 + 255) / 256, 256>>>(wo, gwob, nw4);

    dim3 gg(MROWS / 128, DMODEL / 128);   // (32, 8)
    gemm_mma_kernel<<<gg, 256>>>(gqb, gwqb, bq, nullptr, nullptr, gq2);
    gemm_mma_kernel<<<gg, 256>>>(gkb, gwkb, bk, nullptr, nullptr, gk2);
    gemm_mma_kernel<<<gg, 256>>>(gvb, gwvb, bv, nullptr, nullptr, gv2);

    attn_mma_kernel<<<dim3(SEQ / 64, NH, NB), 128>>>(gq2, gk2, gv2, mask, gctx);

    gemm_mma_kernel<<<gg, 256>>>(gctx, gwob, bo, Q, out, nullptr);
    ln_kernel<<<MROWS, 256>>>(out, gamma, beta);
}

// round 6
// speedup vs baseline: 4.6376x; 1.3284x over previous
#include <cuda_runtime.h>
#include <cuda_bf16.h>
#include <cstdint>

#define DMODEL 1024
#define SEQ    2048
#define NB     2
#define NH     16
#define HD     64
#define MROWS  (NB * SEQ)          // 4096
#define NT     (SEQ / 64)          // 32 k-tiles in attention

// ====================== PTX helpers (base sm_103 features only) ==============
__device__ __forceinline__ uint32_t smem_u32(const void* p) {
    uint32_t a;
    asm("{ .reg .u64 t; cvta.to.shared.u64 t, %1; cvt.u32.u64 %0, t; }"
        : "=r"(a) : "l"(p));
    return a;
}
__device__ __forceinline__ void ldsm4(uint32_t* r, uint32_t addr) {
    asm volatile("ldmatrix.sync.aligned.m8n8.x4.shared.b16 {%0,%1,%2,%3}, [%4];"
                 : "=r"(r[0]), "=r"(r[1]), "=r"(r[2]), "=r"(r[3]) : "r"(addr));
}
__device__ __forceinline__ void ldsm4t(uint32_t* r, uint32_t addr) {
    asm volatile("ldmatrix.sync.aligned.m8n8.x4.trans.shared.b16 {%0,%1,%2,%3}, [%4];"
                 : "=r"(r[0]), "=r"(r[1]), "=r"(r[2]), "=r"(r[3]) : "r"(addr));
}
__device__ __forceinline__ void mma_bf16(float* c, const uint32_t* a, const uint32_t* b) {
    asm volatile(
        "mma.sync.aligned.m16n8k16.row.col.f32.bf16.bf16.f32 "
        "{%0,%1,%2,%3}, {%4,%5,%6,%7}, {%8,%9}, {%0,%1,%2,%3};"
        : "+f"(c[0]), "+f"(c[1]), "+f"(c[2]), "+f"(c[3])
        : "r"(a[0]), "r"(a[1]), "r"(a[2]), "r"(a[3]), "r"(b[0]), "r"(b[1]));
}
#define CP_ASYNC16(dst, src) \
    asm volatile("cp.async.cg.shared.global [%0], [%1], 16;" \
                 :: "r"(dst), "l"(src) : "memory")
#define CP_COMMIT() asm volatile("cp.async.commit_group;" ::: "memory")
#define CP_WAIT(n)  asm volatile("cp.async.wait_group %0;" :: "n"(n) : "memory")

__device__ __forceinline__ uint32_t pack2(float lo, float hi) {
    __nv_bfloat162 t = __floats2bfloat162_rn(lo, hi);
    return *reinterpret_cast<uint32_t*>(&t);
}
// exp(x), x <= 0, on fma/alu pipes (MUFU stays free). rel err ~1e-5.
__device__ __forceinline__ float fexp(float x) {
    float t = fmaxf(x * 1.44269504088896f, -126.0f);
    int   e = __float2int_rd(t);
    float f = t - (float)e;
    float p = 1.53569209e-4f;
    p = fmaf(p, f, 1.33978521e-3f);
    p = fmaf(p, f, 9.61817249e-3f);
    p = fmaf(p, f, 5.55041087e-2f);
    p = fmaf(p, f, 2.40226507e-1f);
    p = fmaf(p, f, 6.93147181e-1f);
    p = fmaf(p, f, 1.0f);
    return p * __int_as_float((e + 127) << 23);
}

// ====================== scratch ==============================================
__device__ __nv_bfloat16 g_qb [MROWS * DMODEL];
__device__ __nv_bfloat16 g_kb [MROWS * DMODEL];
__device__ __nv_bfloat16 g_vb [MROWS * DMODEL];
__device__ __nv_bfloat16 g_q2 [MROWS * DMODEL];
__device__ __nv_bfloat16 g_k2 [MROWS * DMODEL];
__device__ __nv_bfloat16 g_v2 [MROWS * DMODEL];
__device__ __nv_bfloat16 g_ctx[MROWS * DMODEL];
__device__ __nv_bfloat16 g_wqb[DMODEL * DMODEL];
__device__ __nv_bfloat16 g_wkb[DMODEL * DMODEL];
__device__ __nv_bfloat16 g_wvb[DMODEL * DMODEL];
__device__ __nv_bfloat16 g_wob[DMODEL * DMODEL];

// ====================== converts =============================================
__global__ __launch_bounds__(256) void f2bf_kernel(
    const float* __restrict__ in, __nv_bfloat16* __restrict__ out, int n4)
{
    int i = blockIdx.x * 256 + threadIdx.x;
    if (i < n4) {
        float4 v = ((const float4*)in)[i];
        ((__nv_bfloat162*)out)[i * 2 + 0] = __floats2bfloat162_rn(v.x, v.y);
        ((__nv_bfloat162*)out)[i * 2 + 1] = __floats2bfloat162_rn(v.z, v.w);
    }
}
__global__ __launch_bounds__(256) void f2bf_w4_kernel(
    const float* __restrict__ w0, const float* __restrict__ w1,
    const float* __restrict__ w2, const float* __restrict__ w3,
    __nv_bfloat16* __restrict__ o0, __nv_bfloat16* __restrict__ o1,
    __nv_bfloat16* __restrict__ o2, __nv_bfloat16* __restrict__ o3)
{
    const int y = blockIdx.y;
    const float* in = (y == 0) ? w0 : (y == 1) ? w1 : (y == 2) ? w2 : w3;
    __nv_bfloat16* out = (y == 0) ? o0 : (y == 1) ? o1 : (y == 2) ? o2 : o3;
    int i = blockIdx.x * 256 + threadIdx.x;     // n4 = 256K exactly
    float4 v = ((const float4*)in)[i];
    ((__nv_bfloat162*)out)[i * 2 + 0] = __floats2bfloat162_rn(v.x, v.y);
    ((__nv_bfloat162*)out)[i * 2 + 1] = __floats2bfloat162_rn(v.z, v.w);
}

// ====================== GEMM core (templated epilogue) =======================
#define GSTR 40   // smem row stride bf16: 80B = 5*16B -> cp.async aligned, ldsm conflict-free
// Epi: void(const float acc[4], int row0, int col) for each 16x8 C-fragment.
template <typename Epi>
__device__ __forceinline__ void gemm_body(
    const __nv_bfloat16* __restrict__ A, const __nv_bfloat16* __restrict__ W,
    Epi epi)
{
    __shared__ __nv_bfloat16 As[2][128 * GSTR];
    __shared__ __nv_bfloat16 Ws[2][128 * GSTR];
    const int tid = threadIdx.x;
    const int wid = tid >> 5, lid = tid & 31;
    const int wm = wid >> 2, wn = wid & 3;
    const int bm = blockIdx.x * 128, bn = blockIdx.y * 128;
    const uint32_t as_u = smem_u32(As), ws_u = smem_u32(Ws);
    float acc[4][4][4] = {};

    auto load_tile = [&](int buf, int k0) {
#pragma unroll
        for (int i = 0; i < 2; i++) {
            int c = tid * 2 + i;
            int row = c >> 2, col = (c & 3) << 3;
            CP_ASYNC16(as_u + ((uint32_t)buf * (128 * GSTR) + row * GSTR + col) * 2,
                       A + (size_t)(bm + row) * DMODEL + k0 + col);
            CP_ASYNC16(ws_u + ((uint32_t)buf * (128 * GSTR) + row * GSTR + col) * 2,
                       W + (size_t)(bn + row) * DMODEL + k0 + col);
        }
    };

    load_tile(0, 0); CP_COMMIT();
    for (int k0 = 0; k0 < DMODEL; k0 += 32) {
        const int buf = (k0 >> 5) & 1;
        if (k0 + 32 < DMODEL) { load_tile(buf ^ 1, k0 + 32); CP_COMMIT(); CP_WAIT(1); }
        else                  { CP_WAIT(0); }
        __syncthreads();
        const uint32_t ab = as_u + (uint32_t)buf * (128 * GSTR * 2);
        const uint32_t wb = ws_u + (uint32_t)buf * (128 * GSTR * 2);
#pragma unroll
        for (int ks = 0; ks < 2; ks++) {
            uint32_t aF[4][4];
#pragma unroll
            for (int mt = 0; mt < 4; mt++)
                ldsm4(aF[mt], ab + (((wm * 64 + mt * 16 + (lid & 15)) * GSTR
                                     + ks * 16 + (lid >> 4) * 8) << 1));
            uint32_t bF[2][4];
#pragma unroll
            for (int p = 0; p < 2; p++)
                ldsm4(bF[p], wb + (((wn * 32 + p * 16 + ((lid >> 4) & 1) * 8 + (lid & 7)) * GSTR
                                    + ks * 16 + ((lid >> 3) & 1) * 8) << 1));
#pragma unroll
            for (int mt = 0; mt < 4; mt++)
#pragma unroll
                for (int nt = 0; nt < 4; nt++)
                    mma_bf16(acc[mt][nt], aF[mt], &bF[nt >> 1][(nt & 1) * 2]);
        }
        __syncthreads();
    }

    const int lr = lid >> 2, lc2 = (lid & 3) * 2;
#pragma unroll
    for (int mt = 0; mt < 4; mt++) {
        const int row0 = bm + wm * 64 + mt * 16 + lr;
#pragma unroll
        for (int nt = 0; nt < 4; nt++) {
            const int col = bn + wn * 32 + nt * 8 + lc2;
            epi(acc[mt][nt], row0, col);
        }
    }
}

// QKV fused projection: blockIdx.z selects (input, weight, bias, output); bf16 out
__global__ __launch_bounds__(256) void gemm_qkv_kernel(
    const __nv_bfloat16* __restrict__ qb, const __nv_bfloat16* __restrict__ kb,
    const __nv_bfloat16* __restrict__ vb,
    const __nv_bfloat16* __restrict__ wq, const __nv_bfloat16* __restrict__ wk,
    const __nv_bfloat16* __restrict__ wv,
    const float* __restrict__ bq, const float* __restrict__ bk,
    const float* __restrict__ bv,
    __nv_bfloat16* __restrict__ q2, __nv_bfloat16* __restrict__ k2,
    __nv_bfloat16* __restrict__ v2)
{
    const int z = blockIdx.z;
    const __nv_bfloat16* A = (z == 0) ? qb : (z == 1) ? kb : vb;
    const __nv_bfloat16* W = (z == 0) ? wq : (z == 1) ? wk : wv;
    const float* bias       = (z == 0) ? bq : (z == 1) ? bk : bv;
    __nv_bfloat16* Cb       = (z == 0) ? q2 : (z == 1) ? k2 : v2;
    gemm_body(A, W, [&](const float* a4, int row0, int col) {
        const float b0 = bias[col], b1 = bias[col + 1];
        *(uint32_t*)(Cb + (size_t)row0 * DMODEL + col)       = pack2(a4[0] + b0, a4[1] + b1);
        *(uint32_t*)(Cb + (size_t)(row0 + 8) * DMODEL + col) = pack2(a4[2] + b0, a4[3] + b1);
    });
}

// Output projection: f32 out + bias + residual
__global__ __launch_bounds__(256) void gemm_out_kernel(
    const __nv_bfloat16* __restrict__ A, const __nv_bfloat16* __restrict__ W,
    const float* __restrict__ bias, const float* __restrict__ resid,
    float* __restrict__ Cf)
{
    gemm_body(A, W, [&](const float* a4, int row0, int col) {
        const float b0 = bias[col], b1 = bias[col + 1];
        float2 r0 = *(const float2*)(resid + (size_t)row0 * DMODEL + col);
        float2 r1 = *(const float2*)(resid + (size_t)(row0 + 8) * DMODEL + col);
        *(float2*)(Cf + (size_t)row0 * DMODEL + col) =
            make_float2(a4[0] + b0 + r0.x, a4[1] + b1 + r0.y);
        *(float2*)(Cf + (size_t)(row0 + 8) * DMODEL + col) =
            make_float2(a4[2] + b0 + r1.x, a4[3] + b1 + r1.y);
    });
}

// ====================== mma flash attention ==================================
// 8 warps; CTA = 128 q-rows of one (head, batch); warp = 16 rows.
// K/V double-buffered via cp.async. Mask int32 nonzero -> -1e9.
#define ASTR 72   // 144B = 9*16B: cp.async aligned + ldsm conflict-free
#define ATTN_DSMEM ((128 * ASTR + 4 * 64 * ASTR) * 2)
__global__ __launch_bounds__(256) void attn_mma_kernel(
    const __nv_bfloat16* __restrict__ qg, const __nv_bfloat16* __restrict__ kg,
    const __nv_bfloat16* __restrict__ vg, const int* __restrict__ mask,
    __nv_bfloat16* __restrict__ ctx)
{
    extern __shared__ __nv_bfloat16 dsm[];
    __nv_bfloat16* Qs = dsm;                       // 128 x ASTR
    __nv_bfloat16* Ks = Qs + 128 * ASTR;           // 2 bufs x 64 x ASTR
    __nv_bfloat16* Vs = Ks + 2 * 64 * ASTR;        // 2 bufs x 64 x ASTR

    const int tid = threadIdx.x;
    const int wid = tid >> 5, lid = tid & 31;
    const int qt = blockIdx.x, h = blockIdx.y, b = blockIdx.z;

    const size_t head_off = (size_t)b * (SEQ * DMODEL) + (size_t)h * (SEQ * HD);
    const __nv_bfloat16* qh = qg + head_off + (size_t)qt * (128 * HD);
    const __nv_bfloat16* kh = kg + head_off;
    const __nv_bfloat16* vh = vg + head_off;

    const uint32_t qs_u = smem_u32(Qs), ks_u = smem_u32(Ks), vs_u = smem_u32(Vs);

    auto loadKV = [&](int buf, int kt) {
        const __nv_bfloat16* kp = kh + (size_t)kt * (64 * HD);
        const __nv_bfloat16* vp = vh + (size_t)kt * (64 * HD);
        const uint32_t kb_ = ks_u + (uint32_t)buf * (64 * ASTR * 2);
        const uint32_t vb_ = vs_u + (uint32_t)buf * (64 * ASTR * 2);
#pragma unroll
        for (int i = 0; i < 2; i++) {
            int c = tid * 2 + i;                   // 0..511 chunks of 16B
            int row = c >> 3, col = (c & 7) << 3;
            CP_ASYNC16(kb_ + (uint32_t)(row * ASTR + col) * 2, kp + row * HD + col);
            CP_ASYNC16(vb_ + (uint32_t)(row * ASTR + col) * 2, vp + row * HD + col);
        }
    };

    loadKV(0, 0); CP_COMMIT();

    // Q tile: 128 x 64 bf16, contiguous slab
#pragma unroll
    for (int i = 0; i < 4; i++) {
        int idx = tid + i * 256;                   // 0..1023 8-elem groups
        int row = idx >> 3, c8 = (idx & 7) << 3;
        *(uint4*)&Qs[row * ASTR + c8] = *(const uint4*)(qh + row * HD + c8);
    }
    __syncthreads();

    uint32_t aQ[4][4];
#pragma unroll
    for (int kk = 0; kk < 4; kk++)
        ldsm4(aQ[kk], qs_u + (((wid * 16 + (lid & 15)) * ASTR
                               + kk * 16 + (lid >> 4) * 8) << 1));

    float accO[8][4] = {};
    float m0 = -1e30f, m1 = -1e30f, l0 = 0.f, l1 = 0.f;

    const int r0l = qt * 128 + wid * 16 + (lid >> 2);
    const int* mk0 = mask + (size_t)b * SEQ * SEQ + (size_t)r0l * SEQ;
    const int* mk1 = mk0 + 8 * SEQ;

    const int nhib = (lid >> 4) & 1;
    const int khib = (lid >> 3) & 1;
    const int l7   = lid & 7;

    for (int kt = 0; kt < NT; kt++) {
        const int buf = kt & 1;
        if (kt + 1 < NT) { loadKV(buf ^ 1, kt + 1); CP_COMMIT(); CP_WAIT(1); }
        else             { CP_WAIT(0); }
        __syncthreads();
        const uint32_t kb_ = ks_u + (uint32_t)buf * (64 * ASTR * 2);
        const uint32_t vb_ = vs_u + (uint32_t)buf * (64 * ASTR * 2);

        // ---- S = Q K^T ----
        float accS[8][4] = {};
#pragma unroll
        for (int kk = 0; kk < 4; kk++) {
            uint32_t bK[4][4];
#pragma unroll
            for (int p = 0; p < 4; p++)
                ldsm4(bK[p], kb_ + (((p * 16 + nhib * 8 + l7) * ASTR
                                     + kk * 16 + khib * 8) << 1));
#pragma unroll
            for (int nt = 0; nt < 8; nt++)
                mma_bf16(accS[nt], aQ[kk], &bK[nt >> 1][(nt & 1) * 2]);
        }

        // ---- mask + scale + online softmax ----
        const int cb = kt * 64 + 2 * (lid & 3);
        float mx0 = -3e38f, mx1 = -3e38f;
#pragma unroll
        for (int nt = 0; nt < 8; nt++) {
            int c = cb + nt * 8;
            int2 ma = *(const int2*)(mk0 + c);
            int2 mb = *(const int2*)(mk1 + c);
            accS[nt][0] = ma.x ? -1e9f : accS[nt][0] * 0.125f;
            accS[nt][1] = ma.y ? -1e9f : accS[nt][1] * 0.125f;
            accS[nt][2] = mb.x ? -1e9f : accS[nt][2] * 0.125f;
            accS[nt][3] = mb.y ? -1e9f : accS[nt][3] * 0.125f;
            mx0 = fmaxf(mx0, fmaxf(accS[nt][0], accS[nt][1]));
            mx1 = fmaxf(mx1, fmaxf(accS[nt][2], accS[nt][3]));
        }
        mx0 = fmaxf(mx0, __shfl_xor_sync(0xffffffffu, mx0, 1));
        mx0 = fmaxf(mx0, __shfl_xor_sync(0xffffffffu, mx0, 2));
        mx1 = fmaxf(mx1, __shfl_xor_sync(0xffffffffu, mx1, 1));
        mx1 = fmaxf(mx1, __shfl_xor_sync(0xffffffffu, mx1, 2));

        const float mn0 = fmaxf(m0, mx0), mn1 = fmaxf(m1, mx1);
        const float al0 = fexp(m0 - mn0), al1 = fexp(m1 - mn1);
        m0 = mn0; m1 = mn1;

        float rs0 = 0.f, rs1 = 0.f;
#pragma unroll
        for (int nt = 0; nt < 8; nt++) {
            accS[nt][0] = fexp(accS[nt][0] - m0);
            accS[nt][1] = fexp(accS[nt][1] - m0);
            accS[nt][2] = fexp(accS[nt][2] - m1);
            accS[nt][3] = fexp(accS[nt][3] - m1);
            rs0 += accS[nt][0] + accS[nt][1];
            rs1 += accS[nt][2] + accS[nt][3];
        }
        rs0 += __shfl_xor_sync(0xffffffffu, rs0, 1);
        rs0 += __shfl_xor_sync(0xffffffffu, rs0, 2);
        rs1 += __shfl_xor_sync(0xffffffffu, rs1, 1);
        rs1 += __shfl_xor_sync(0xffffffffu, rs1, 2);
        l0 = l0 * al0 + rs0;
        l1 = l1 * al1 + rs1;
#pragma unroll
        for (int nt = 0; nt < 8; nt++) {
            accO[nt][0] *= al0; accO[nt][1] *= al0;
            accO[nt][2] *= al1; accO[nt][3] *= al1;
        }

        // ---- P -> bf16 A-frags (register-resident) ----
        uint32_t aP[4][4];
#pragma unroll
        for (int kk = 0; kk < 4; kk++) {
            aP[kk][0] = pack2(accS[2 * kk][0],     accS[2 * kk][1]);
            aP[kk][1] = pack2(accS[2 * kk][2],     accS[2 * kk][3]);
            aP[kk][2] = pack2(accS[2 * kk + 1][0], accS[2 * kk + 1][1]);
            aP[kk][3] = pack2(accS[2 * kk + 1][2], accS[2 * kk + 1][3]);
        }

        // ---- O += P V ----
#pragma unroll
        for (int kk = 0; kk < 4; kk++) {
            uint32_t bV[4][4];
#pragma unroll
            for (int p = 0; p < 4; p++)
                ldsm4t(bV[p], vb_ + (((kk * 16 + khib * 8 + l7) * ASTR
                                      + p * 16 + nhib * 8) << 1));
#pragma unroll
            for (int nt = 0; nt < 8; nt++)
                mma_bf16(accO[nt], aP[kk], &bV[nt >> 1][(nt & 1) * 2]);
        }
        __syncthreads();
    }

    // ---- write ctx (head-concat layout) ----
    const float inv0 = 1.f / l0, inv1 = 1.f / l1;
    __nv_bfloat16* crow0 = ctx + (size_t)b * (SEQ * DMODEL) + (size_t)r0l * DMODEL + h * HD;
    __nv_bfloat16* crow1 = crow0 + (size_t)8 * DMODEL;
#pragma unroll
    for (int nt = 0; nt < 8; nt++) {
        int c = nt * 8 + 2 * (lid & 3);
        *(uint32_t*)(crow0 + c) = pack2(accO[nt][0] * inv0, accO[nt][1] * inv0);
        *(uint32_t*)(crow1 + c) = pack2(accO[nt][2] * inv1, accO[nt][3] * inv1);
    }
}

// ====================== LayerNorm ===========================================
__global__ __launch_bounds__(256) void ln_kernel(
    float* __restrict__ x, const float* __restrict__ gamma,
    const float* __restrict__ beta)
{
    __shared__ float ss[8], ssq[8];
    const int row = blockIdx.x;
    const int tid = threadIdx.x;
    float* xr = x + (size_t)row * DMODEL;

    float4 v = *(const float4*)(xr + tid * 4);
    float s  = v.x + v.y + v.z + v.w;
    float sq = v.x * v.x + v.y * v.y + v.z * v.z + v.w * v.w;
#pragma unroll
    for (int o = 16; o >= 1; o >>= 1) {
        s  += __shfl_xor_sync(0xffffffffu, s,  o);
        sq += __shfl_xor_sync(0xffffffffu, sq, o);
    }
    if ((tid & 31) == 0) { ss[tid >> 5] = s; ssq[tid >> 5] = sq; }
    __syncthreads();
    float tot = 0.f, totq = 0.f;
#pragma unroll
    for (int i = 0; i < 8; i++) { tot += ss[i]; totq += ssq[i]; }

    const float mean = tot * (1.0f / DMODEL);
    const float var  = totq * (1.0f / DMODEL) - mean * mean;
    const float rstd = rsqrtf(var + 1e-5f);

    float4 g = *(const float4*)(gamma + tid * 4);
    float4 bb = *(const float4*)(beta + tid * 4);
    float4 o;
    o.x = (v.x - mean) * rstd * g.x + bb.x;
    o.y = (v.y - mean) * rstd * g.y + bb.y;
    o.z = (v.z - mean) * rstd * g.z + bb.z;
    o.w = (v.w - mean) * rstd * g.w + bb.w;
    *(float4*)(xr + tid * 4) = o;
}

// ====================== launch ==============================================
extern "C" void kernel_launch(void* const* d_in, const int* in_sizes, int n_in,
                              void* d_out, int out_size) {
    const float* Q  = (const float*)d_in[0];
    const float* K  = (const float*)d_in[1];
    const float* V  = (const float*)d_in[2];
    const int*   mask = (const int*)d_in[3];
    const float* wq = (const float*)d_in[4];
    const float* bq = (const float*)d_in[5];
    const float* wk = (const float*)d_in[6];
    const float* bk = (const float*)d_in[7];
    const float* wv = (const float*)d_in[8];
    const float* bv = (const float*)d_in[9];
    const float* wo = (const float*)d_in[10];
    const float* bo = (const float*)d_in[11];
    const float* gamma = (const float*)d_in[12];
    const float* beta  = (const float*)d_in[13];
    float* out = (float*)d_out;

    __nv_bfloat16 *gqb, *gkb, *gvb, *gq2, *gk2, *gv2, *gctx;
    __nv_bfloat16 *gwqb, *gwkb, *gwvb, *gwob;
    cudaGetSymbolAddress((void**)&gqb,  g_qb);
    cudaGetSymbolAddress((void**)&gkb,  g_kb);
    cudaGetSymbolAddress((void**)&gvb,  g_vb);
    cudaGetSymbolAddress((void**)&gq2,  g_q2);
    cudaGetSymbolAddress((void**)&gk2,  g_k2);
    cudaGetSymbolAddress((void**)&gv2,  g_v2);
    cudaGetSymbolAddress((void**)&gctx, g_ctx);
    cudaGetSymbolAddress((void**)&gwqb, g_wqb);
    cudaGetSymbolAddress((void**)&gwkb, g_wkb);
    cudaGetSymbolAddress((void**)&gwvb, g_wvb);
    cudaGetSymbolAddress((void**)&gwob, g_wob);

    cudaFuncSetAttribute(attn_mma_kernel,
                         cudaFuncAttributeMaxDynamicSharedMemorySize, ATTN_DSMEM);

    const int nin4 = MROWS * DMODEL / 4;      // 1M float4
    f2bf_kernel<<<(nin4 + 255) / 256, 256>>>(Q, gqb, nin4);          // launch 0
    f2bf_kernel<<<(nin4 + 255) / 256, 256>>>(K, gkb, nin4);          // launch 1
    f2bf_kernel<<<(nin4 + 255) / 256, 256>>>(V, gvb, nin4);          // launch 2
    f2bf_w4_kernel<<<dim3(1024, 4), 256>>>(wq, wk, wv, wo,           // launch 3
                                           gwqb, gwkb, gwvb, gwob);

    dim3 gg(MROWS / 128, DMODEL / 128, 3);    // (32, 8, 3)
    gemm_qkv_kernel<<<gg, 256>>>(gqb, gkb, gvb, gwqb, gwkb, gwvb,    // launch 4
                                 bq, bk, bv, gq2, gk2, gv2);

    attn_mma_kernel<<<dim3(SEQ / 128, NH, NB), 256, ATTN_DSMEM>>>(   // launch 5 (profiled)
        gq2, gk2, gv2, mask, gctx);

    gemm_out_kernel<<<dim3(MROWS / 128, DMODEL / 128), 256>>>(       // launch 6
        gctx, gwob, bo, Q, out);
    ln_kernel<<<MROWS, 256>>>(out, gamma, beta);                     // launch 7
}

// round 7
// speedup vs baseline: 5.0840x; 1.0963x over previous
#include <cuda_runtime.h>
#include <cuda_bf16.h>
#include <cstdint>

#define DMODEL 1024
#define SEQ    2048
#define NB     2
#define NH     16
#define HD     64
#define MROWS  (NB * SEQ)          // 4096
#define NT     (SEQ / 64)          // 32 k-tiles in attention
#define SCL2E  0.180336880f        // 0.125 * log2(e)
#define MASKB2 (-1.442695040e9f)   // -1e9 * log2(e)

// ====================== PTX helpers (base sm_103 features only) ==============
__device__ __forceinline__ uint32_t smem_u32(const void* p) {
    uint32_t a;
    asm("{ .reg .u64 t; cvta.to.shared.u64 t, %1; cvt.u32.u64 %0, t; }"
        : "=r"(a) : "l"(p));
    return a;
}
__device__ __forceinline__ void ldsm4(uint32_t* r, uint32_t addr) {
    asm volatile("ldmatrix.sync.aligned.m8n8.x4.shared.b16 {%0,%1,%2,%3}, [%4];"
                 : "=r"(r[0]), "=r"(r[1]), "=r"(r[2]), "=r"(r[3]) : "r"(addr));
}
__device__ __forceinline__ void ldsm4t(uint32_t* r, uint32_t addr) {
    asm volatile("ldmatrix.sync.aligned.m8n8.x4.trans.shared.b16 {%0,%1,%2,%3}, [%4];"
                 : "=r"(r[0]), "=r"(r[1]), "=r"(r[2]), "=r"(r[3]) : "r"(addr));
}
__device__ __forceinline__ void mma_bf16(float* c, const uint32_t* a, const uint32_t* b) {
    asm volatile(
        "mma.sync.aligned.m16n8k16.row.col.f32.bf16.bf16.f32 "
        "{%0,%1,%2,%3}, {%4,%5,%6,%7}, {%8,%9}, {%0,%1,%2,%3};"
        : "+f"(c[0]), "+f"(c[1]), "+f"(c[2]), "+f"(c[3])
        : "r"(a[0]), "r"(a[1]), "r"(a[2]), "r"(a[3]), "r"(b[0]), "r"(b[1]));
}
#define CP_ASYNC16(dst, src) \
    asm volatile("cp.async.cg.shared.global [%0], [%1], 16;" \
                 :: "r"(dst), "l"(src) : "memory")
#define CP_COMMIT() asm volatile("cp.async.commit_group;" ::: "memory")
#define CP_WAIT(n)  asm volatile("cp.async.wait_group %0;" :: "n"(n) : "memory")

__device__ __forceinline__ uint32_t pack2(float lo, float hi) {
    __nv_bfloat162 t = __floats2bfloat162_rn(lo, hi);
    return *reinterpret_cast<uint32_t*>(&t);
}
// 2^x on the MUFU pipe (keeps fma/alu free for the rest of softmax)
__device__ __forceinline__ float fex2(float x) {
    float r;
    asm("ex2.approx.f32 %0, %1;" : "=f"(r) : "f"(x));
    return r;
}

// ====================== scratch ==============================================
__device__ __nv_bfloat16 g_qb [MROWS * DMODEL];
__device__ __nv_bfloat16 g_kb [MROWS * DMODEL];
__device__ __nv_bfloat16 g_vb [MROWS * DMODEL];
__device__ __nv_bfloat16 g_q2 [MROWS * DMODEL];
__device__ __nv_bfloat16 g_k2 [MROWS * DMODEL];
__device__ __nv_bfloat16 g_v2 [MROWS * DMODEL];
__device__ __nv_bfloat16 g_ctx[MROWS * DMODEL];
__device__ __nv_bfloat16 g_wqb[DMODEL * DMODEL];
__device__ __nv_bfloat16 g_wkb[DMODEL * DMODEL];
__device__ __nv_bfloat16 g_wvb[DMODEL * DMODEL];
__device__ __nv_bfloat16 g_wob[DMODEL * DMODEL];
__device__ __nv_bfloat16 g_bias[NB * SEQ * SEQ];   // log2-domain additive mask bias

// ====================== converts =============================================
__global__ __launch_bounds__(256) void f2bf_kernel(
    const float* __restrict__ in, __nv_bfloat16* __restrict__ out, int n4)
{
    int i = blockIdx.x * 256 + threadIdx.x;
    if (i < n4) {
        float4 v = ((const float4*)in)[i];
        ((__nv_bfloat162*)out)[i * 2 + 0] = __floats2bfloat162_rn(v.x, v.y);
        ((__nv_bfloat162*)out)[i * 2 + 1] = __floats2bfloat162_rn(v.z, v.w);
    }
}
__global__ __launch_bounds__(256) void f2bf_w4_kernel(
    const float* __restrict__ w0, const float* __restrict__ w1,
    const float* __restrict__ w2, const float* __restrict__ w3,
    __nv_bfloat16* __restrict__ o0, __nv_bfloat16* __restrict__ o1,
    __nv_bfloat16* __restrict__ o2, __nv_bfloat16* __restrict__ o3)
{
    const int y = blockIdx.y;
    const float* in = (y == 0) ? w0 : (y == 1) ? w1 : (y == 2) ? w2 : w3;
    __nv_bfloat16* out = (y == 0) ? o0 : (y == 1) ? o1 : (y == 2) ? o2 : o3;
    int i = blockIdx.x * 256 + threadIdx.x;     // n4 = 256K exactly
    float4 v = ((const float4*)in)[i];
    ((__nv_bfloat162*)out)[i * 2 + 0] = __floats2bfloat162_rn(v.x, v.y);
    ((__nv_bfloat162*)out)[i * 2 + 1] = __floats2bfloat162_rn(v.z, v.w);
}
// mask(int32 nonzero) -> bf16 log2-domain bias (-1e9*log2e or 0)
__global__ __launch_bounds__(256) void mask2bias_kernel(
    const int* __restrict__ mask, __nv_bfloat16* __restrict__ bias)
{
    int i = blockIdx.x * 256 + threadIdx.x;     // quad index; n/4 exact
    int4 m = ((const int4*)mask)[i];
    __nv_bfloat162 lo = __floats2bfloat162_rn(m.x ? MASKB2 : 0.f, m.y ? MASKB2 : 0.f);
    __nv_bfloat162 hi = __floats2bfloat162_rn(m.z ? MASKB2 : 0.f, m.w ? MASKB2 : 0.f);
    ((__nv_bfloat162*)bias)[i * 2 + 0] = lo;
    ((__nv_bfloat162*)bias)[i * 2 + 1] = hi;
}

// ====================== GEMM core (templated epilogue) =======================
#define GSTR 40   // smem row stride bf16: 80B = 5*16B -> cp.async aligned, ldsm conflict-free
template <typename Epi>
__device__ __forceinline__ void gemm_body(
    const __nv_bfloat16* __restrict__ A, const __nv_bfloat16* __restrict__ W,
    Epi epi)
{
    __shared__ __nv_bfloat16 As[2][128 * GSTR];
    __shared__ __nv_bfloat16 Ws[2][128 * GSTR];
    const int tid = threadIdx.x;
    const int wid = tid >> 5, lid = tid & 31;
    const int wm = wid >> 2, wn = wid & 3;
    const int bm = blockIdx.x * 128, bn = blockIdx.y * 128;
    const uint32_t as_u = smem_u32(As), ws_u = smem_u32(Ws);
    float acc[4][4][4] = {};

    auto load_tile = [&](int buf, int k0) {
#pragma unroll
        for (int i = 0; i < 2; i++) {
            int c = tid * 2 + i;
            int row = c >> 2, col = (c & 3) << 3;
            CP_ASYNC16(as_u + ((uint32_t)buf * (128 * GSTR) + row * GSTR + col) * 2,
                       A + (size_t)(bm + row) * DMODEL + k0 + col);
            CP_ASYNC16(ws_u + ((uint32_t)buf * (128 * GSTR) + row * GSTR + col) * 2,
                       W + (size_t)(bn + row) * DMODEL + k0 + col);
        }
    };

    load_tile(0, 0); CP_COMMIT();
    for (int k0 = 0; k0 < DMODEL; k0 += 32) {
        const int buf = (k0 >> 5) & 1;
        if (k0 + 32 < DMODEL) { load_tile(buf ^ 1, k0 + 32); CP_COMMIT(); CP_WAIT(1); }
        else                  { CP_WAIT(0); }
        __syncthreads();
        const uint32_t ab = as_u + (uint32_t)buf * (128 * GSTR * 2);
        const uint32_t wb = ws_u + (uint32_t)buf * (128 * GSTR * 2);
#pragma unroll
        for (int ks = 0; ks < 2; ks++) {
            uint32_t aF[4][4];
#pragma unroll
            for (int mt = 0; mt < 4; mt++)
                ldsm4(aF[mt], ab + (((wm * 64 + mt * 16 + (lid & 15)) * GSTR
                                     + ks * 16 + (lid >> 4) * 8) << 1));
            uint32_t bF[2][4];
#pragma unroll
            for (int p = 0; p < 2; p++)
                ldsm4(bF[p], wb + (((wn * 32 + p * 16 + ((lid >> 4) & 1) * 8 + (lid & 7)) * GSTR
                                    + ks * 16 + ((lid >> 3) & 1) * 8) << 1));
#pragma unroll
            for (int mt = 0; mt < 4; mt++)
#pragma unroll
                for (int nt = 0; nt < 4; nt++)
                    mma_bf16(acc[mt][nt], aF[mt], &bF[nt >> 1][(nt & 1) * 2]);
        }
        __syncthreads();
    }

    const int lr = lid >> 2, lc2 = (lid & 3) * 2;
#pragma unroll
    for (int mt = 0; mt < 4; mt++) {
        const int row0 = bm + wm * 64 + mt * 16 + lr;
#pragma unroll
        for (int nt = 0; nt < 4; nt++) {
            const int col = bn + wn * 32 + nt * 8 + lc2;
            epi(acc[mt][nt], row0, col);
        }
    }
}

// QKV fused projection: blockIdx.z selects (input, weight, bias, output); bf16 out
__global__ __launch_bounds__(256) void gemm_qkv_kernel(
    const __nv_bfloat16* __restrict__ qb, const __nv_bfloat16* __restrict__ kb,
    const __nv_bfloat16* __restrict__ vb,
    const __nv_bfloat16* __restrict__ wq, const __nv_bfloat16* __restrict__ wk,
    const __nv_bfloat16* __restrict__ wv,
    const float* __restrict__ bq, const float* __restrict__ bk,
    const float* __restrict__ bv,
    __nv_bfloat16* __restrict__ q2, __nv_bfloat16* __restrict__ k2,
    __nv_bfloat16* __restrict__ v2)
{
    const int z = blockIdx.z;
    const __nv_bfloat16* A = (z == 0) ? qb : (z == 1) ? kb : vb;
    const __nv_bfloat16* W = (z == 0) ? wq : (z == 1) ? wk : wv;
    const float* bias       = (z == 0) ? bq : (z == 1) ? bk : bv;
    __nv_bfloat16* Cb       = (z == 0) ? q2 : (z == 1) ? k2 : v2;
    gemm_body(A, W, [&](const float* a4, int row0, int col) {
        const float b0 = bias[col], b1 = bias[col + 1];
        *(uint32_t*)(Cb + (size_t)row0 * DMODEL + col)       = pack2(a4[0] + b0, a4[1] + b1);
        *(uint32_t*)(Cb + (size_t)(row0 + 8) * DMODEL + col) = pack2(a4[2] + b0, a4[3] + b1);
    });
}

// Output projection: f32 out + bias + residual
__global__ __launch_bounds__(256) void gemm_out_kernel(
    const __nv_bfloat16* __restrict__ A, const __nv_bfloat16* __restrict__ W,
    const float* __restrict__ bias, const float* __restrict__ resid,
    float* __restrict__ Cf)
{
    gemm_body(A, W, [&](const float* a4, int row0, int col) {
        const float b0 = bias[col], b1 = bias[col + 1];
        float2 r0 = *(const float2*)(resid + (size_t)row0 * DMODEL + col);
        float2 r1 = *(const float2*)(resid + (size_t)(row0 + 8) * DMODEL + col);
        *(float2*)(Cf + (size_t)row0 * DMODEL + col) =
            make_float2(a4[0] + b0 + r0.x, a4[1] + b1 + r0.y);
        *(float2*)(Cf + (size_t)(row0 + 8) * DMODEL + col) =
            make_float2(a4[2] + b0 + r1.x, a4[3] + b1 + r1.y);
    });
}

// ====================== mma flash attention ==================================
// 8 warps; CTA = 128 q-rows of one (head, batch); warp = 16 rows.
// K/V double-buffered via cp.async. Softmax in log2 domain, ex2 on MUFU.
#define ASTR 72   // 144B = 9*16B: cp.async aligned + ldsm conflict-free
#define ATTN_DSMEM ((128 * ASTR + 4 * 64 * ASTR) * 2)
__global__ __launch_bounds__(256) void attn_mma_kernel(
    const __nv_bfloat16* __restrict__ qg, const __nv_bfloat16* __restrict__ kg,
    const __nv_bfloat16* __restrict__ vg, const __nv_bfloat16* __restrict__ biasg,
    __nv_bfloat16* __restrict__ ctx)
{
    extern __shared__ __nv_bfloat16 dsm[];
    __nv_bfloat16* Qs = dsm;                       // 128 x ASTR
    __nv_bfloat16* Ks = Qs + 128 * ASTR;           // 2 bufs x 64 x ASTR
    __nv_bfloat16* Vs = Ks + 2 * 64 * ASTR;        // 2 bufs x 64 x ASTR

    const int tid = threadIdx.x;
    const int wid = tid >> 5, lid = tid & 31;
    const int qt = blockIdx.x, h = blockIdx.y, b = blockIdx.z;

    const size_t head_off = (size_t)b * (SEQ * DMODEL) + (size_t)h * (SEQ * HD);
    const __nv_bfloat16* qh = qg + head_off + (size_t)qt * (128 * HD);
    const __nv_bfloat16* kh = kg + head_off;
    const __nv_bfloat16* vh = vg + head_off;

    const uint32_t qs_u = smem_u32(Qs), ks_u = smem_u32(Ks), vs_u = smem_u32(Vs);

    auto loadKV = [&](int buf, int kt) {
        const __nv_bfloat16* kp = kh + (size_t)kt * (64 * HD);
        const __nv_bfloat16* vp = vh + (size_t)kt * (64 * HD);
        const uint32_t kb_ = ks_u + (uint32_t)buf * (64 * ASTR * 2);
        const uint32_t vb_ = vs_u + (uint32_t)buf * (64 * ASTR * 2);
#pragma unroll
        for (int i = 0; i < 2; i++) {
            int c = tid * 2 + i;                   // 0..511 chunks of 16B
            int row = c >> 3, col = (c & 7) << 3;
            CP_ASYNC16(kb_ + (uint32_t)(row * ASTR + col) * 2, kp + row * HD + col);
            CP_ASYNC16(vb_ + (uint32_t)(row * ASTR + col) * 2, vp + row * HD + col);
        }
    };

    loadKV(0, 0); CP_COMMIT();

    // Q tile: 128 x 64 bf16, contiguous slab
#pragma unroll
    for (int i = 0; i < 4; i++) {
        int idx = tid + i * 256;                   // 0..1023 8-elem groups
        int row = idx >> 3, c8 = (idx & 7) << 3;
        *(uint4*)&Qs[row * ASTR + c8] = *(const uint4*)(qh + row * HD + c8);
    }
    __syncthreads();

    uint32_t aQ[4][4];
#pragma unroll
    for (int kk = 0; kk < 4; kk++)
        ldsm4(aQ[kk], qs_u + (((wid * 16 + (lid & 15)) * ASTR
                               + kk * 16 + (lid >> 4) * 8) << 1));

    float accO[8][4] = {};
    float m0 = -1e30f, m1 = -1e30f, l0 = 0.f, l1 = 0.f;

    const int r0l = qt * 128 + wid * 16 + (lid >> 2);
    const __nv_bfloat16* bs0 = biasg + (size_t)b * SEQ * SEQ + (size_t)r0l * SEQ;
    const __nv_bfloat16* bs1 = bs0 + (size_t)8 * SEQ;

    const int nhib = (lid >> 4) & 1;
    const int khib = (lid >> 3) & 1;
    const int l7   = lid & 7;

    for (int kt = 0; kt < NT; kt++) {
        const int buf = kt & 1;
        if (kt + 1 < NT) { loadKV(buf ^ 1, kt + 1); CP_COMMIT(); CP_WAIT(1); }
        else             { CP_WAIT(0); }
        __syncthreads();
        const uint32_t kb_ = ks_u + (uint32_t)buf * (64 * ASTR * 2);
        const uint32_t vb_ = vs_u + (uint32_t)buf * (64 * ASTR * 2);

        // ---- S = Q K^T ----
        float accS[8][4] = {};
#pragma unroll
        for (int kk = 0; kk < 4; kk++) {
            uint32_t bK[4][4];
#pragma unroll
            for (int p = 0; p < 4; p++)
                ldsm4(bK[p], kb_ + (((p * 16 + nhib * 8 + l7) * ASTR
                                     + kk * 16 + khib * 8) << 1));
#pragma unroll
            for (int nt = 0; nt < 8; nt++)
                mma_bf16(accS[nt], aQ[kk], &bK[nt >> 1][(nt & 1) * 2]);
        }

        // ---- log2-domain: s2 = s * (0.125*log2e) + bias2 ; max ----
        const int cb = kt * 64 + 2 * (lid & 3);
        float mx0 = -3e38f, mx1 = -3e38f;
#pragma unroll
        for (int nt = 0; nt < 8; nt++) {
            int c = cb + nt * 8;
            float2 f0 = __bfloat1622float2(*(const __nv_bfloat162*)(bs0 + c));
            float2 f1 = __bfloat1622float2(*(const __nv_bfloat162*)(bs1 + c));
            accS[nt][0] = fmaf(accS[nt][0], SCL2E, f0.x);
            accS[nt][1] = fmaf(accS[nt][1], SCL2E, f0.y);
            accS[nt][2] = fmaf(accS[nt][2], SCL2E, f1.x);
            accS[nt][3] = fmaf(accS[nt][3], SCL2E, f1.y);
            mx0 = fmaxf(mx0, fmaxf(accS[nt][0], accS[nt][1]));
            mx1 = fmaxf(mx1, fmaxf(accS[nt][2], accS[nt][3]));
        }
        mx0 = fmaxf(mx0, __shfl_xor_sync(0xffffffffu, mx0, 1));
        mx0 = fmaxf(mx0, __shfl_xor_sync(0xffffffffu, mx0, 2));
        mx1 = fmaxf(mx1, __shfl_xor_sync(0xffffffffu, mx1, 1));
        mx1 = fmaxf(mx1, __shfl_xor_sync(0xffffffffu, mx1, 2));

        const float mn0 = fmaxf(m0, mx0), mn1 = fmaxf(m1, mx1);
        const float al0 = fex2(m0 - mn0), al1 = fex2(m1 - mn1);
        m0 = mn0; m1 = mn1;

        float rs0 = 0.f, rs1 = 0.f;
#pragma unroll
        for (int nt = 0; nt < 8; nt++) {
            accS[nt][0] = fex2(accS[nt][0] - m0);
            accS[nt][1] = fex2(accS[nt][1] - m0);
            accS[nt][2] = fex2(accS[nt][2] - m1);
            accS[nt][3] = fex2(accS[nt][3] - m1);
            rs0 += accS[nt][0] + accS[nt][1];
            rs1 += accS[nt][2] + accS[nt][3];
        }
        rs0 += __shfl_xor_sync(0xffffffffu, rs0, 1);
        rs0 += __shfl_xor_sync(0xffffffffu, rs0, 2);
        rs1 += __shfl_xor_sync(0xffffffffu, rs1, 1);
        rs1 += __shfl_xor_sync(0xffffffffu, rs1, 2);
        l0 = l0 * al0 + rs0;
        l1 = l1 * al1 + rs1;
#pragma unroll
        for (int nt = 0; nt < 8; nt++) {
            accO[nt][0] *= al0; accO[nt][1] *= al0;
            accO[nt][2] *= al1; accO[nt][3] *= al1;
        }

        // ---- P -> bf16 A-frags (register-resident) ----
        uint32_t aP[4][4];
#pragma unroll
        for (int kk = 0; kk < 4; kk++) {
            aP[kk][0] = pack2(accS[2 * kk][0],     accS[2 * kk][1]);
            aP[kk][1] = pack2(accS[2 * kk][2],     accS[2 * kk][3]);
            aP[kk][2] = pack2(accS[2 * kk + 1][0], accS[2 * kk + 1][1]);
            aP[kk][3] = pack2(accS[2 * kk + 1][2], accS[2 * kk + 1][3]);
        }

        // ---- O += P V ----
#pragma unroll
        for (int kk = 0; kk < 4; kk++) {
            uint32_t bV[4][4];
#pragma unroll
            for (int p = 0; p < 4; p++)
                ldsm4t(bV[p], vb_ + (((kk * 16 + khib * 8 + l7) * ASTR
                                      + p * 16 + nhib * 8) << 1));
#pragma unroll
            for (int nt = 0; nt < 8; nt++)
                mma_bf16(accO[nt], aP[kk], &bV[nt >> 1][(nt & 1) * 2]);
        }
        __syncthreads();
    }

    // ---- write ctx (head-concat layout) ----
    const float inv0 = 1.f / l0, inv1 = 1.f / l1;
    __nv_bfloat16* crow0 = ctx + (size_t)b * (SEQ * DMODEL) + (size_t)r0l * DMODEL + h * HD;
    __nv_bfloat16* crow1 = crow0 + (size_t)8 * DMODEL;
#pragma unroll
    for (int nt = 0; nt < 8; nt++) {
        int c = nt * 8 + 2 * (lid & 3);
        *(uint32_t*)(crow0 + c) = pack2(accO[nt][0] * inv0, accO[nt][1] * inv0);
        *(uint32_t*)(crow1 + c) = pack2(accO[nt][2] * inv1, accO[nt][3] * inv1);
    }
}

// ====================== LayerNorm ===========================================
__global__ __launch_bounds__(256) void ln_kernel(
    float* __restrict__ x, const float* __restrict__ gamma,
    const float* __restrict__ beta)
{
    __shared__ float ss[8], ssq[8];
    const int row = blockIdx.x;
    const int tid = threadIdx.x;
    float* xr = x + (size_t)row * DMODEL;

    float4 v = *(const float4*)(xr + tid * 4);
    float s  = v.x + v.y + v.z + v.w;
    float sq = v.x * v.x + v.y * v.y + v.z * v.z + v.w * v.w;
#pragma unroll
    for (int o = 16; o >= 1; o >>= 1) {
        s  += __shfl_xor_sync(0xffffffffu, s,  o);
        sq += __shfl_xor_sync(0xffffffffu, sq, o);
    }
    if ((tid & 31) == 0) { ss[tid >> 5] = s; ssq[tid >> 5] = sq; }
    __syncthreads();
    float tot = 0.f, totq = 0.f;
#pragma unroll
    for (int i = 0; i < 8; i++) { tot += ss[i]; totq += ssq[i]; }

    const float mean = tot * (1.0f / DMODEL);
    const float var  = totq * (1.0f / DMODEL) - mean * mean;
    const float rstd = rsqrtf(var + 1e-5f);

    float4 g = *(const float4*)(gamma + tid * 4);
    float4 bb = *(const float4*)(beta + tid * 4);
    float4 o;
    o.x = (v.x - mean) * rstd * g.x + bb.x;
    o.y = (v.y - mean) * rstd * g.y + bb.y;
    o.z = (v.z - mean) * rstd * g.z + bb.z;
    o.w = (v.w - mean) * rstd * g.w + bb.w;
    *(float4*)(xr + tid * 4) = o;
}

// ====================== launch ==============================================
extern "C" void kernel_launch(void* const* d_in, const int* in_sizes, int n_in,
                              void* d_out, int out_size) {
    const float* Q  = (const float*)d_in[0];
    const float* K  = (const float*)d_in[1];
    const float* V  = (const float*)d_in[2];
    const int*   mask = (const int*)d_in[3];
    const float* wq = (const float*)d_in[4];
    const float* bq = (const float*)d_in[5];
    const float* wk = (const float*)d_in[6];
    const float* bk = (const float*)d_in[7];
    const float* wv = (const float*)d_in[8];
    const float* bv = (const float*)d_in[9];
    const float* wo = (const float*)d_in[10];
    const float* bo = (const float*)d_in[11];
    const float* gamma = (const float*)d_in[12];
    const float* beta  = (const float*)d_in[13];
    float* out = (float*)d_out;

    __nv_bfloat16 *gqb, *gkb, *gvb, *gq2, *gk2, *gv2, *gctx, *gbias;
    __nv_bfloat16 *gwqb, *gwkb, *gwvb, *gwob;
    cudaGetSymbolAddress((void**)&gqb,  g_qb);
    cudaGetSymbolAddress((void**)&gkb,  g_kb);
    cudaGetSymbolAddress((void**)&gvb,  g_vb);
    cudaGetSymbolAddress((void**)&gq2,  g_q2);
    cudaGetSymbolAddress((void**)&gk2,  g_k2);
    cudaGetSymbolAddress((void**)&gv2,  g_v2);
    cudaGetSymbolAddress((void**)&gctx, g_ctx);
    cudaGetSymbolAddress((void**)&gbias, g_bias);
    cudaGetSymbolAddress((void**)&gwqb, g_wqb);
    cudaGetSymbolAddress((void**)&gwkb, g_wkb);
    cudaGetSymbolAddress((void**)&gwvb, g_wvb);
    cudaGetSymbolAddress((void**)&gwob, g_wob);

    cudaFuncSetAttribute(attn_mma_kernel,
                         cudaFuncAttributeMaxDynamicSharedMemorySize, ATTN_DSMEM);

    const int nin4 = MROWS * DMODEL / 4;      // 1M float4
    f2bf_kernel<<<(nin4 + 255) / 256, 256>>>(Q, gqb, nin4);
    f2bf_kernel<<<(nin4 + 255) / 256, 256>>>(K, gkb, nin4);
    f2bf_kernel<<<(nin4 + 255) / 256, 256>>>(V, gvb, nin4);
    f2bf_w4_kernel<<<dim3(1024, 4), 256>>>(wq, wk, wv, wo,
                                           gwqb, gwkb, gwvb, gwob);
    mask2bias_kernel<<<(NB * SEQ * SEQ / 4 + 255) / 256, 256>>>(mask, gbias);

    dim3 gg(MROWS / 128, DMODEL / 128, 3);    // (32, 8, 3)
    gemm_qkv_kernel<<<gg, 256>>>(gqb, gkb, gvb, gwqb, gwkb, gwvb,
                                 bq, bk, bv, gq2, gk2, gv2);

    attn_mma_kernel<<<dim3(SEQ / 128, NH, NB), 256, ATTN_DSMEM>>>(
        gq2, gk2, gv2, gbias, gctx);

    gemm_out_kernel<<<dim3(MROWS / 128, DMODEL / 128), 256>>>(
        gctx, gwob, bo, Q, out);
    ln_kernel<<<MROWS, 256>>>(out, gamma, beta);
}